// round 10
// baseline (speedup 1.0000x reference)
#include <cuda_runtime.h>
#include <cuda_bf16.h>
#include <cstdint>

// Problem constants
#define B_   2
#define L_   2048
#define HID_ 2048
#define H_   32
#define KVH_ 8
#define D_   64

#define NX  ((size_t)B_ * L_ * HID_)
#define NQ  ((size_t)B_ * L_ * H_ * D_)
#define NKV ((size_t)B_ * L_ * KVH_ * D_)
#define NWQ ((size_t)H_ * D_ * HID_)
#define NWK ((size_t)KVH_ * D_ * HID_)
#define NWO ((size_t)HID_ * H_ * D_)

__device__ __nv_bfloat16 g_xhi  [NX],      g_xlo  [NX];
__device__ __nv_bfloat16 g_wqhi [NWQ],     g_wqlo [NWQ];
__device__ __nv_bfloat16 g_wkvhi[2 * NWK], g_wkvlo[2 * NWK];   // wk rows then wv rows
__device__ __nv_bfloat16 g_wohi [NWO],     g_wolo [NWO];
__device__ __nv_bfloat16 g_ahi  [NX],      g_alo  [NX];
__device__ __nv_bfloat16 g_qhi  [NQ],      g_qlo  [NQ];
__device__ __nv_bfloat16 g_khi  [NKV],     g_klo  [NKV];
__device__ __nv_bfloat16 g_vhi  [NKV],     g_vlo  [NKV];

// ---------------------------------------------------------------------------
// PTX helpers (legacy mma path only — sm_100 base target has no tcgen05)
// ---------------------------------------------------------------------------
__device__ __forceinline__ void ldm_x4(uint32_t* r, uint32_t addr) {
    asm volatile("ldmatrix.sync.aligned.m8n8.x4.shared.b16 {%0,%1,%2,%3}, [%4];"
                 : "=r"(r[0]), "=r"(r[1]), "=r"(r[2]), "=r"(r[3]) : "r"(addr));
}
__device__ __forceinline__ void ldm_x4_t(uint32_t* r, uint32_t addr) {
    asm volatile("ldmatrix.sync.aligned.m8n8.x4.trans.shared.b16 {%0,%1,%2,%3}, [%4];"
                 : "=r"(r[0]), "=r"(r[1]), "=r"(r[2]), "=r"(r[3]) : "r"(addr));
}
__device__ __forceinline__ void mma16816(float* d, const uint32_t* a, const uint32_t* b) {
    asm volatile("mma.sync.aligned.m16n8k16.row.col.f32.bf16.bf16.f32 "
                 "{%0,%1,%2,%3}, {%4,%5,%6,%7}, {%8,%9}, {%0,%1,%2,%3};"
                 : "+f"(d[0]), "+f"(d[1]), "+f"(d[2]), "+f"(d[3])
                 : "r"(a[0]), "r"(a[1]), "r"(a[2]), "r"(a[3]), "r"(b[0]), "r"(b[1]));
}
#define CP_ASYNC16(dst, src) \
    asm volatile("cp.async.cg.shared.global [%0], [%1], 16;" :: "r"(dst), "l"(src))

__device__ __forceinline__ void split_store(__nv_bfloat16* hi, __nv_bfloat16* lo,
                                            size_t idx, float v0, float v1)
{
    __nv_bfloat16 h0 = __float2bfloat16(v0), h1 = __float2bfloat16(v1);
    *(__nv_bfloat162*)(hi + idx) = __halves2bfloat162(h0, h1);
    *(__nv_bfloat162*)(lo + idx) = __halves2bfloat162(
        __float2bfloat16(v0 - __bfloat162float(h0)),
        __float2bfloat16(v1 - __bfloat162float(h1)));
}

// ---------------------------------------------------------------------------
// Split fp32 -> bf16 hi + bf16 lo
// ---------------------------------------------------------------------------
__global__ void split_kernel(const float* __restrict__ in,
                             __nv_bfloat16* __restrict__ hi,
                             __nv_bfloat16* __restrict__ lo, int n4)
{
    int i = blockIdx.x * blockDim.x + threadIdx.x;
    if (i >= n4) return;
    float4 v = ((const float4*)in)[i];
    __nv_bfloat16 h0 = __float2bfloat16(v.x);
    __nv_bfloat16 h1 = __float2bfloat16(v.y);
    __nv_bfloat16 h2 = __float2bfloat16(v.z);
    __nv_bfloat16 h3 = __float2bfloat16(v.w);
    ((__nv_bfloat162*)hi)[2 * i + 0] = __halves2bfloat162(h0, h1);
    ((__nv_bfloat162*)hi)[2 * i + 1] = __halves2bfloat162(h2, h3);
    ((__nv_bfloat162*)lo)[2 * i + 0] = __halves2bfloat162(
        __float2bfloat16(v.x - __bfloat162float(h0)),
        __float2bfloat16(v.y - __bfloat162float(h1)));
    ((__nv_bfloat162*)lo)[2 * i + 1] = __halves2bfloat162(
        __float2bfloat16(v.z - __bfloat162float(h2)),
        __float2bfloat16(v.w - __bfloat162float(h3)));
}

// ---------------------------------------------------------------------------
// Tensor-core NT GEMM, bf16x3 (round-8 config — proven):
// CTA 64x128, 128 threads, BK=32, 2-stage, 3 CTAs/SM.
// MODE 0: fp32 C;  MODE 1: rope*0.125 split;  MODE 2: K rope / V split
// ---------------------------------------------------------------------------
#define GA_HI 0
#define GA_LO 5120
#define GB_HI 10240
#define GB_LO 20480
#define GSTG  30720
#define GEMM_SMEM (2 * GSTG)    // 61440

template<int MODE>
__global__ __launch_bounds__(128, 3) void gemm_bf16x3(
    const __nv_bfloat16* __restrict__ Ahi, const __nv_bfloat16* __restrict__ Alo,
    const __nv_bfloat16* __restrict__ Bhi, const __nv_bfloat16* __restrict__ Blo,
    float* __restrict__ C,
    __nv_bfloat16* __restrict__ Ohi, __nv_bfloat16* __restrict__ Olo,
    __nv_bfloat16* __restrict__ O2hi, __nv_bfloat16* __restrict__ O2lo,
    const float* __restrict__ fc, const float* __restrict__ fs,
    int M, int N, int K)
{
    extern __shared__ __align__(16) char smem_raw[];
    const uint32_t sbase = (uint32_t)__cvta_generic_to_shared(smem_raw);
    const int tid  = threadIdx.x;
    const int lane = tid & 31;
    const int warp = tid >> 5;
    const int wm   = warp & 1;
    const int wn   = warp >> 1;
    const int bm   = blockIdx.y * 64;
    const int bn   = blockIdx.x * 128;

    const __nv_bfloat16* gA[2] = { Ahi + (size_t)bm * K, Alo + (size_t)bm * K };
    const __nv_bfloat16* gB[2] = { Bhi + (size_t)bn * K, Blo + (size_t)bn * K };

    float c[2][8][4];
#pragma unroll
    for (int i = 0; i < 2; i++)
#pragma unroll
        for (int j = 0; j < 8; j++)
#pragma unroll
            for (int q = 0; q < 4; q++) c[i][j][q] = 0.0f;

    auto load_stage = [&](int stg, int k0) {
        uint32_t sb = sbase + stg * GSTG;
#pragma unroll
        for (int arr = 0; arr < 2; arr++)
#pragma unroll
            for (int it = 0; it < 2; it++) {
                int idx = tid + it * 128;
                int row = idx >> 2, c4 = idx & 3;
                const void* g = gA[arr] + (size_t)row * K + k0 + c4 * 8;
                CP_ASYNC16(sb + (arr ? GA_LO : GA_HI) + row * 80 + c4 * 16, g);
            }
#pragma unroll
        for (int arr = 0; arr < 2; arr++)
#pragma unroll
            for (int it = 0; it < 4; it++) {
                int idx = tid + it * 128;
                int row = idx >> 2, c4 = idx & 3;
                const void* g = gB[arr] + (size_t)row * K + k0 + c4 * 8;
                CP_ASYNC16(sb + (arr ? GB_LO : GB_HI) + row * 80 + c4 * 16, g);
            }
        asm volatile("cp.async.commit_group;");
    };

    load_stage(0, 0);
    const int KT = K >> 5;
    for (int kt = 0; kt < KT; kt++) {
        if (kt + 1 < KT) {
            load_stage((kt + 1) & 1, (kt + 1) * 32);
            asm volatile("cp.async.wait_group 1;");
        } else {
            asm volatile("cp.async.wait_group 0;");
        }
        __syncthreads();

        uint32_t sb = sbase + (kt & 1) * GSTG;
#pragma unroll
        for (int s16 = 0; s16 < 2; s16++) {
            const int ko = s16 * 16;
            uint32_t a_hi[2][4], a_lo[2][4], b_hi[4][4], b_lo[4][4];
#pragma unroll
            for (int i = 0; i < 2; i++) {
                uint32_t ar = sb + GA_HI + (wm * 32 + i * 16 + (lane & 15)) * 80
                                 + (ko + (lane >> 4) * 8) * 2;
                ldm_x4(a_hi[i], ar);
                ldm_x4(a_lo[i], ar + (GA_LO - GA_HI));
            }
            const int grp = lane >> 3, rr = lane & 7;
#pragma unroll
            for (int jp = 0; jp < 4; jp++) {
                int row = wn * 64 + jp * 16 + (grp >> 1) * 8 + rr;
                uint32_t br = sb + GB_HI + row * 80 + (ko + (grp & 1) * 8) * 2;
                ldm_x4(b_hi[jp], br);
                ldm_x4(b_lo[jp], br + (GB_LO - GB_HI));
            }
#pragma unroll
            for (int i = 0; i < 2; i++)
#pragma unroll
                for (int j = 0; j < 8; j++) {
                    const int jp = j >> 1, off = (j & 1) * 2;
                    mma16816(c[i][j], a_hi[i], &b_hi[jp][off]);
                    mma16816(c[i][j], a_hi[i], &b_lo[jp][off]);
                    mma16816(c[i][j], a_lo[i], &b_hi[jp][off]);
                }
        }
        __syncthreads();
    }

    const int rowb = bm + wm * 32 + (lane >> 2);
    const int colb = bn + wn * 64 + (lane & 3) * 2;

    if (MODE == 0) {
#pragma unroll
        for (int i = 0; i < 2; i++)
#pragma unroll
            for (int j = 0; j < 8; j++) {
                int row = rowb + i * 16;
                int col = colb + j * 8;
                *(float2*)&C[(size_t)row * N + col]       = make_float2(c[i][j][0], c[i][j][1]);
                *(float2*)&C[(size_t)(row + 8) * N + col] = make_float2(c[i][j][2], c[i][j][3]);
            }
    } else {
#pragma unroll
        for (int i = 0; i < 2; i++)
#pragma unroll
            for (int j = 0; j < 8; j++) {
                int col = colb + j * 8;
#pragma unroll
                for (int rr2 = 0; rr2 < 2; rr2++) {
                    int row = rowb + i * 16 + rr2 * 8;
                    float v0 = c[i][j][rr2 * 2], v1 = c[i][j][rr2 * 2 + 1];
                    if (MODE == 1 || col < 512) {
                        int l = row & (L_ - 1);
                        int p = (col & 63) >> 1;
                        float cc = fc[l * 32 + p], ss = fs[l * 32 + p];
                        float sca = (MODE == 1) ? 0.125f : 1.0f;
                        float o0 = (v0 * cc - v1 * ss) * sca;
                        float o1 = (v0 * ss + v1 * cc) * sca;
                        v0 = o0; v1 = o1;
                    }
                    if (MODE == 1) {
                        split_store(Ohi, Olo, (size_t)row * N + col, v0, v1);
                    } else {
                        if (col < 512) split_store(Ohi,  Olo,  (size_t)row * 512 + col, v0, v1);
                        else           split_store(O2hi, O2lo, (size_t)row * 512 + col - 512, v0, v1);
                    }
                }
            }
    }
}

// ---------------------------------------------------------------------------
// Tensor-core causal GQA flash attention, bf16x3.
// CTA = 128 queries x (head, batch); 8 warps x 16 query rows; 64-key stages,
// double buffered. smem 110.6KB -> 2 CTAs/SM = 16 warps/SM.
// Warp-level compute identical to the proven round-4 kernel.
// ---------------------------------------------------------------------------
#define SROW 72
#define AQ_BYTES   18432                      // one Q array: 128*72*2
#define AKV_BYTES  9216                       // one KV array: 64*72*2
#define ASTG_BYTES 36864                      // 4 KV arrays
#define ATTN_SMEM  (2 * AQ_BYTES + 2 * ASTG_BYTES)   // 110592

__global__ __launch_bounds__(256, 2) void attn_mma(
    const __nv_bfloat16* __restrict__ Qhi, const __nv_bfloat16* __restrict__ Qlo,
    const __nv_bfloat16* __restrict__ Khi, const __nv_bfloat16* __restrict__ Klo,
    const __nv_bfloat16* __restrict__ Vhi, const __nv_bfloat16* __restrict__ Vlo,
    __nv_bfloat16* __restrict__ Ohi, __nv_bfloat16* __restrict__ Olo)
{
    extern __shared__ __align__(16) char smem_raw[];
    const uint32_t sb = (uint32_t)__cvta_generic_to_shared(smem_raw);
    const int qb  = (int)(gridDim.x - 1 - blockIdx.x);   // heavy tiles first
    const int h   = blockIdx.y;
    const int b   = blockIdx.z;
    const int kvh = h >> 2;
    const int tid  = threadIdx.x;
    const int lane = tid & 31;
    const int warp = tid >> 5;                           // 0..7

    // ---- async load Q (hi+lo): 128 rows ----
    {
        const size_t qoff = ((size_t)(b * L_ + qb * 128) * H_ + h) * D_;
        const __nv_bfloat16* qs[2] = { Qhi + qoff, Qlo + qoff };
#pragma unroll
        for (int arr = 0; arr < 2; arr++)
#pragma unroll
            for (int it = 0; it < 4; it++) {
                int idx = tid + it * 256, row = idx >> 3, ch = idx & 7;
                uint32_t dst = sb + arr * AQ_BYTES + (row * SROW + ch * 8) * 2;
                const void* src = qs[arr] + (size_t)row * (H_ * D_) + ch * 8;
                CP_ASYNC16(dst, src);
            }
    }
    auto load_kv = [&](int stg, int kb) {
        const size_t koff = ((size_t)(b * L_ + kb * 64) * KVH_ + kvh) * D_;
        const __nv_bfloat16* srcs[4] = { Khi + koff, Klo + koff, Vhi + koff, Vlo + koff };
        uint32_t base = sb + 2 * AQ_BYTES + stg * ASTG_BYTES;
#pragma unroll
        for (int arr = 0; arr < 4; arr++)
#pragma unroll
            for (int it = 0; it < 2; it++) {
                int idx = tid + it * 256, row = idx >> 3, ch = idx & 7;
                uint32_t dst = base + arr * AKV_BYTES + (row * SROW + ch * 8) * 2;
                const void* src = srcs[arr] + (size_t)row * (KVH_ * D_) + ch * 8;
                CP_ASYNC16(dst, src);
            }
    };
    load_kv(0, 0);
    asm volatile("cp.async.commit_group;");

    float O[8][4];
#pragma unroll
    for (int nt = 0; nt < 8; nt++)
#pragma unroll
        for (int q = 0; q < 4; q++) O[nt][q] = 0.0f;
    float m0 = -1e30f, m1 = -1e30f, l0 = 0.0f, l1 = 0.0f;

    const int grp = lane >> 3;
    const int wrow_lo = qb * 128 + warp * 16;            // warp's lowest query row
    const int KB = 2 * qb + 2;                           // key blocks of 64

    for (int kb = 0; kb < KB; kb++) {
        if (kb + 1 < KB) {
            load_kv((kb + 1) & 1, kb + 1);
            asm volatile("cp.async.commit_group;");
            asm volatile("cp.async.wait_group 1;");
        } else {
            asm volatile("cp.async.wait_group 0;");
        }
        __syncthreads();

        // warp-uniform skip: entire warp row range below this key block
        if (kb * 64 <= wrow_lo + 15) {
            const uint32_t stb = sb + 2 * AQ_BYTES + (kb & 1) * ASTG_BYTES;

            float sc[8][4];
#pragma unroll
            for (int nt = 0; nt < 8; nt++)
#pragma unroll
                for (int q = 0; q < 4; q++) sc[nt][q] = 0.0f;

#pragma unroll
            for (int ks = 0; ks < 4; ks++) {
                uint32_t ah[4], al[4];
                uint32_t qa = sb + ((warp * 16 + (lane & 15)) * SROW
                                    + ks * 16 + (lane >> 4) * 8) * 2;
                ldm_x4(ah, qa);
                ldm_x4(al, qa + AQ_BYTES);
#pragma unroll
                for (int jn = 0; jn < 4; jn++) {
                    uint32_t ka = stb + ((jn * 16 + (grp >> 1) * 8 + (lane & 7)) * SROW
                                         + ks * 16 + (grp & 1) * 8) * 2;
                    uint32_t bh[4], bl[4];
                    ldm_x4(bh, ka);
                    ldm_x4(bl, ka + AKV_BYTES);
                    mma16816(sc[2 * jn],     ah, &bh[0]);
                    mma16816(sc[2 * jn],     ah, &bl[0]);
                    mma16816(sc[2 * jn],     al, &bh[0]);
                    mma16816(sc[2 * jn + 1], ah, &bh[2]);
                    mma16816(sc[2 * jn + 1], ah, &bl[2]);
                    mma16816(sc[2 * jn + 1], al, &bh[2]);
                }
            }

            // ---- causal mask (only blocks that can touch the diagonal) ----
            const int r0g = wrow_lo + (lane >> 2);
            if (kb * 64 + 63 > wrow_lo) {
                const int cb = kb * 64 + (lane & 3) * 2;
#pragma unroll
                for (int nt = 0; nt < 8; nt++) {
                    int c = cb + nt * 8;
                    if (c     > r0g)     sc[nt][0] = -1e30f;
                    if (c + 1 > r0g)     sc[nt][1] = -1e30f;
                    if (c     > r0g + 8) sc[nt][2] = -1e30f;
                    if (c + 1 > r0g + 8) sc[nt][3] = -1e30f;
                }
            }

            // ---- online softmax ----
            float mx0 = sc[0][0], mx1 = sc[0][2];
#pragma unroll
            for (int nt = 0; nt < 8; nt++) {
                mx0 = fmaxf(mx0, fmaxf(sc[nt][0], sc[nt][1]));
                mx1 = fmaxf(mx1, fmaxf(sc[nt][2], sc[nt][3]));
            }
            mx0 = fmaxf(mx0, __shfl_xor_sync(0xffffffffu, mx0, 1));
            mx0 = fmaxf(mx0, __shfl_xor_sync(0xffffffffu, mx0, 2));
            mx1 = fmaxf(mx1, __shfl_xor_sync(0xffffffffu, mx1, 1));
            mx1 = fmaxf(mx1, __shfl_xor_sync(0xffffffffu, mx1, 2));
            float mn0 = fmaxf(m0, mx0), mn1 = fmaxf(m1, mx1);
            float a0 = __expf(m0 - mn0), a1 = __expf(m1 - mn1);
            m0 = mn0; m1 = mn1;
            float s0 = 0.0f, s1 = 0.0f;
#pragma unroll
            for (int nt = 0; nt < 8; nt++) {
                sc[nt][0] = __expf(sc[nt][0] - mn0);
                sc[nt][1] = __expf(sc[nt][1] - mn0);
                sc[nt][2] = __expf(sc[nt][2] - mn1);
                sc[nt][3] = __expf(sc[nt][3] - mn1);
                s0 += sc[nt][0] + sc[nt][1];
                s1 += sc[nt][2] + sc[nt][3];
            }
            s0 += __shfl_xor_sync(0xffffffffu, s0, 1);
            s0 += __shfl_xor_sync(0xffffffffu, s0, 2);
            s1 += __shfl_xor_sync(0xffffffffu, s1, 1);
            s1 += __shfl_xor_sync(0xffffffffu, s1, 2);
            l0 = l0 * a0 + s0;
            l1 = l1 * a1 + s1;
#pragma unroll
            for (int nt = 0; nt < 8; nt++) {
                O[nt][0] *= a0; O[nt][1] *= a0;
                O[nt][2] *= a1; O[nt][3] *= a1;
            }

            // ---- O += Phi*Vhi + Phi*Vlo + Plo*Vhi ----
#pragma unroll
            for (int ks = 0; ks < 4; ks++) {
                uint32_t ph[4], pl[4];
#pragma unroll
                for (int t = 0; t < 2; t++) {
                    int nt = 2 * ks + t;
#pragma unroll
                    for (int j = 0; j < 2; j++) {
                        float x0 = sc[nt][2 * j], x1 = sc[nt][2 * j + 1];
                        __nv_bfloat16 h0 = __float2bfloat16(x0);
                        __nv_bfloat16 h1 = __float2bfloat16(x1);
                        __nv_bfloat162 hp = __halves2bfloat162(h0, h1);
                        __nv_bfloat162 lp = __halves2bfloat162(
                            __float2bfloat16(x0 - __bfloat162float(h0)),
                            __float2bfloat16(x1 - __bfloat162float(h1)));
                        ph[t * 2 + j] = *(uint32_t*)&hp;
                        pl[t * 2 + j] = *(uint32_t*)&lp;
                    }
                }
#pragma unroll
                for (int dj = 0; dj < 4; dj++) {
                    uint32_t va = stb + 2 * AKV_BYTES
                                + ((ks * 16 + (grp & 1) * 8 + (lane & 7)) * SROW
                                   + dj * 16 + (grp >> 1) * 8) * 2;
                    uint32_t vh[4], vl[4];
                    ldm_x4_t(vh, va);
                    ldm_x4_t(vl, va + AKV_BYTES);
                    mma16816(O[2 * dj],     ph, &vh[0]);
                    mma16816(O[2 * dj],     ph, &vl[0]);
                    mma16816(O[2 * dj],     pl, &vh[0]);
                    mma16816(O[2 * dj + 1], ph, &vh[2]);
                    mma16816(O[2 * dj + 1], ph, &vl[2]);
                    mma16816(O[2 * dj + 1], pl, &vh[2]);
                }
            }
        }
        __syncthreads();
    }

    // ---- epilogue ----
    float i0 = 1.0f / l0, i1 = 1.0f / l1;
    const size_t ro = ((size_t)(b * L_ + qb * 128 + warp * 16 + (lane >> 2)) * H_ + h) * D_
                      + (lane & 3) * 2;
    const size_t r8 = ro + (size_t)8 * H_ * D_;
#pragma unroll
    for (int nt = 0; nt < 8; nt++) {
        split_store(Ohi, Olo, ro + nt * 8, O[nt][0] * i0, O[nt][1] * i0);
        split_store(Ohi, Olo, r8 + nt * 8, O[nt][2] * i1, O[nt][3] * i1);
    }
}

// ---------------------------------------------------------------------------
// Launch
// ---------------------------------------------------------------------------
static inline void run_split(const float* src, __nv_bfloat16* hi, __nv_bfloat16* lo, size_t n)
{
    int n4 = (int)(n / 4);
    split_kernel<<<(n4 + 255) / 256, 256>>>(src, hi, lo, n4);
}

extern "C" void kernel_launch(void* const* d_in, const int* in_sizes, int n_in,
                              void* d_out, int out_size)
{
    const float* x  = (const float*)d_in[0];
    const float* wq = (const float*)d_in[1];
    const float* wk = (const float*)d_in[2];
    const float* wv = (const float*)d_in[3];
    const float* wo = (const float*)d_in[4];
    const float* fc = (const float*)d_in[5];
    const float* fs = (const float*)d_in[6];
    float* out = (float*)d_out;

    __nv_bfloat16 *xhi, *xlo, *wqhi, *wqlo, *wkvhi, *wkvlo, *wohi, *wolo;
    __nv_bfloat16 *ahi, *alo, *qhi, *qlo, *khi, *klo, *vhi, *vlo;
    cudaGetSymbolAddress((void**)&xhi,   g_xhi);   cudaGetSymbolAddress((void**)&xlo,   g_xlo);
    cudaGetSymbolAddress((void**)&wqhi,  g_wqhi);  cudaGetSymbolAddress((void**)&wqlo,  g_wqlo);
    cudaGetSymbolAddress((void**)&wkvhi, g_wkvhi); cudaGetSymbolAddress((void**)&wkvlo, g_wkvlo);
    cudaGetSymbolAddress((void**)&wohi,  g_wohi);  cudaGetSymbolAddress((void**)&wolo,  g_wolo);
    cudaGetSymbolAddress((void**)&ahi,   g_ahi);   cudaGetSymbolAddress((void**)&alo,   g_alo);
    cudaGetSymbolAddress((void**)&qhi,   g_qhi);   cudaGetSymbolAddress((void**)&qlo,   g_qlo);
    cudaGetSymbolAddress((void**)&khi,   g_khi);   cudaGetSymbolAddress((void**)&klo,   g_klo);
    cudaGetSymbolAddress((void**)&vhi,   g_vhi);   cudaGetSymbolAddress((void**)&vlo,   g_vlo);

    const int M = B_ * L_;                       // 4096

    cudaFuncSetAttribute(gemm_bf16x3<0>, cudaFuncAttributeMaxDynamicSharedMemorySize, GEMM_SMEM);
    cudaFuncSetAttribute(gemm_bf16x3<1>, cudaFuncAttributeMaxDynamicSharedMemorySize, GEMM_SMEM);
    cudaFuncSetAttribute(gemm_bf16x3<2>, cudaFuncAttributeMaxDynamicSharedMemorySize, GEMM_SMEM);
    cudaFuncSetAttribute(attn_mma, cudaFuncAttributeMaxDynamicSharedMemorySize, ATTN_SMEM);

    // Splits: x, wq, wk->wkv[0:512], wv->wkv[512:1024], wo
    run_split(x,  xhi,  xlo,  NX);
    run_split(wq, wqhi, wqlo, NWQ);
    run_split(wk, wkvhi,       wkvlo,       NWK);
    run_split(wv, wkvhi + NWK, wkvlo + NWK, NWK);
    run_split(wo, wohi, wolo, NWO);

    // Q projection, fused rope+scale+split epilogue
    gemm_bf16x3<1><<<dim3((H_ * D_) / 128, M / 64), 128, GEMM_SMEM>>>(
        xhi, xlo, wqhi, wqlo, nullptr, qhi, qlo, nullptr, nullptr, fc, fs,
        M, H_ * D_, HID_);

    // K+V combined projection: rope+split K, split V
    gemm_bf16x3<2><<<dim3(1024 / 128, M / 64), 128, GEMM_SMEM>>>(
        xhi, xlo, wkvhi, wkvlo, nullptr, khi, klo, vhi, vlo, fc, fs,
        M, 1024, HID_);

    // Attention (tensor cores, bf16x3, 128-query CTAs)
    attn_mma<<<dim3(L_ / 128, H_, B_), 256, ATTN_SMEM>>>(
        qhi, qlo, khi, klo, vhi, vlo, ahi, alo);

    // Output projection -> d_out (fp32)
    gemm_bf16x3<0><<<dim3(HID_ / 128, M / 64), 128, GEMM_SMEM>>>(
        ahi, alo, wohi, wolo, out, nullptr, nullptr, nullptr, nullptr, nullptr, nullptr,
        M, HID_, H_ * D_);
}

// round 11
// speedup vs baseline: 1.0199x; 1.0199x over previous
#include <cuda_runtime.h>
#include <cuda_bf16.h>
#include <cstdint>

// Problem constants
#define B_   2
#define L_   2048
#define HID_ 2048
#define H_   32
#define KVH_ 8
#define D_   64

#define NX  ((size_t)B_ * L_ * HID_)
#define NQ  ((size_t)B_ * L_ * H_ * D_)
#define NKV ((size_t)B_ * L_ * KVH_ * D_)
#define NWQ ((size_t)H_ * D_ * HID_)
#define NWK ((size_t)KVH_ * D_ * HID_)
#define NWO ((size_t)HID_ * H_ * D_)

__device__ __nv_bfloat16 g_xhi  [NX],      g_xlo  [NX];
__device__ __nv_bfloat16 g_wqhi [NWQ],     g_wqlo [NWQ];
__device__ __nv_bfloat16 g_wkvhi[2 * NWK], g_wkvlo[2 * NWK];   // wk rows then wv rows
__device__ __nv_bfloat16 g_wohi [NWO],     g_wolo [NWO];
__device__ __nv_bfloat16 g_ahi  [NX],      g_alo  [NX];
__device__ __nv_bfloat16 g_qhi  [NQ],      g_qlo  [NQ];
__device__ __nv_bfloat16 g_khi  [NKV],     g_klo  [NKV];
__device__ __nv_bfloat16 g_vhi  [NKV],     g_vlo  [NKV];

// ---------------------------------------------------------------------------
// PTX helpers (legacy mma path only — sm_100 base target has no tcgen05)
// ---------------------------------------------------------------------------
__device__ __forceinline__ void ldm_x4(uint32_t* r, uint32_t addr) {
    asm volatile("ldmatrix.sync.aligned.m8n8.x4.shared.b16 {%0,%1,%2,%3}, [%4];"
                 : "=r"(r[0]), "=r"(r[1]), "=r"(r[2]), "=r"(r[3]) : "r"(addr));
}
__device__ __forceinline__ void ldm_x4_t(uint32_t* r, uint32_t addr) {
    asm volatile("ldmatrix.sync.aligned.m8n8.x4.trans.shared.b16 {%0,%1,%2,%3}, [%4];"
                 : "=r"(r[0]), "=r"(r[1]), "=r"(r[2]), "=r"(r[3]) : "r"(addr));
}
__device__ __forceinline__ void mma16816(float* d, const uint32_t* a, const uint32_t* b) {
    asm volatile("mma.sync.aligned.m16n8k16.row.col.f32.bf16.bf16.f32 "
                 "{%0,%1,%2,%3}, {%4,%5,%6,%7}, {%8,%9}, {%0,%1,%2,%3};"
                 : "+f"(d[0]), "+f"(d[1]), "+f"(d[2]), "+f"(d[3])
                 : "r"(a[0]), "r"(a[1]), "r"(a[2]), "r"(a[3]), "r"(b[0]), "r"(b[1]));
}
#define CP_ASYNC16(dst, src) \
    asm volatile("cp.async.cg.shared.global [%0], [%1], 16;" :: "r"(dst), "l"(src))

__device__ __forceinline__ void split_store(__nv_bfloat16* hi, __nv_bfloat16* lo,
                                            size_t idx, float v0, float v1)
{
    __nv_bfloat16 h0 = __float2bfloat16(v0), h1 = __float2bfloat16(v1);
    *(__nv_bfloat162*)(hi + idx) = __halves2bfloat162(h0, h1);
    *(__nv_bfloat162*)(lo + idx) = __halves2bfloat162(
        __float2bfloat16(v0 - __bfloat162float(h0)),
        __float2bfloat16(v1 - __bfloat162float(h1)));
}

// ---------------------------------------------------------------------------
// Split fp32 -> bf16 hi + bf16 lo
// ---------------------------------------------------------------------------
__global__ void split_kernel(const float* __restrict__ in,
                             __nv_bfloat16* __restrict__ hi,
                             __nv_bfloat16* __restrict__ lo, int n4)
{
    int i = blockIdx.x * blockDim.x + threadIdx.x;
    if (i >= n4) return;
    float4 v = ((const float4*)in)[i];
    __nv_bfloat16 h0 = __float2bfloat16(v.x);
    __nv_bfloat16 h1 = __float2bfloat16(v.y);
    __nv_bfloat16 h2 = __float2bfloat16(v.z);
    __nv_bfloat16 h3 = __float2bfloat16(v.w);
    ((__nv_bfloat162*)hi)[2 * i + 0] = __halves2bfloat162(h0, h1);
    ((__nv_bfloat162*)hi)[2 * i + 1] = __halves2bfloat162(h2, h3);
    ((__nv_bfloat162*)lo)[2 * i + 0] = __halves2bfloat162(
        __float2bfloat16(v.x - __bfloat162float(h0)),
        __float2bfloat16(v.y - __bfloat162float(h1)));
    ((__nv_bfloat162*)lo)[2 * i + 1] = __halves2bfloat162(
        __float2bfloat16(v.z - __bfloat162float(h2)),
        __float2bfloat16(v.w - __bfloat162float(h3)));
}

// ---------------------------------------------------------------------------
// Tensor-core NT GEMM, bf16x3 (round-8 config — proven):
// CTA 64x128, 128 threads, BK=32, 2-stage, 3 CTAs/SM.
// MODE 0: fp32 C;  MODE 1: rope*0.125 split;  MODE 2: K rope / V split
// ---------------------------------------------------------------------------
#define GA_HI 0
#define GA_LO 5120
#define GB_HI 10240
#define GB_LO 20480
#define GSTG  30720
#define GEMM_SMEM (2 * GSTG)    // 61440

template<int MODE>
__global__ __launch_bounds__(128, 3) void gemm_bf16x3(
    const __nv_bfloat16* __restrict__ Ahi, const __nv_bfloat16* __restrict__ Alo,
    const __nv_bfloat16* __restrict__ Bhi, const __nv_bfloat16* __restrict__ Blo,
    float* __restrict__ C,
    __nv_bfloat16* __restrict__ Ohi, __nv_bfloat16* __restrict__ Olo,
    __nv_bfloat16* __restrict__ O2hi, __nv_bfloat16* __restrict__ O2lo,
    const float* __restrict__ fc, const float* __restrict__ fs,
    int M, int N, int K)
{
    extern __shared__ __align__(16) char smem_raw[];
    const uint32_t sbase = (uint32_t)__cvta_generic_to_shared(smem_raw);
    const int tid  = threadIdx.x;
    const int lane = tid & 31;
    const int warp = tid >> 5;
    const int wm   = warp & 1;
    const int wn   = warp >> 1;
    const int bm   = blockIdx.y * 64;
    const int bn   = blockIdx.x * 128;

    const __nv_bfloat16* gA[2] = { Ahi + (size_t)bm * K, Alo + (size_t)bm * K };
    const __nv_bfloat16* gB[2] = { Bhi + (size_t)bn * K, Blo + (size_t)bn * K };

    float c[2][8][4];
#pragma unroll
    for (int i = 0; i < 2; i++)
#pragma unroll
        for (int j = 0; j < 8; j++)
#pragma unroll
            for (int q = 0; q < 4; q++) c[i][j][q] = 0.0f;

    auto load_stage = [&](int stg, int k0) {
        uint32_t sb = sbase + stg * GSTG;
#pragma unroll
        for (int arr = 0; arr < 2; arr++)
#pragma unroll
            for (int it = 0; it < 2; it++) {
                int idx = tid + it * 128;
                int row = idx >> 2, c4 = idx & 3;
                const void* g = gA[arr] + (size_t)row * K + k0 + c4 * 8;
                CP_ASYNC16(sb + (arr ? GA_LO : GA_HI) + row * 80 + c4 * 16, g);
            }
#pragma unroll
        for (int arr = 0; arr < 2; arr++)
#pragma unroll
            for (int it = 0; it < 4; it++) {
                int idx = tid + it * 128;
                int row = idx >> 2, c4 = idx & 3;
                const void* g = gB[arr] + (size_t)row * K + k0 + c4 * 8;
                CP_ASYNC16(sb + (arr ? GB_LO : GB_HI) + row * 80 + c4 * 16, g);
            }
        asm volatile("cp.async.commit_group;");
    };

    load_stage(0, 0);
    const int KT = K >> 5;
    for (int kt = 0; kt < KT; kt++) {
        if (kt + 1 < KT) {
            load_stage((kt + 1) & 1, (kt + 1) * 32);
            asm volatile("cp.async.wait_group 1;");
        } else {
            asm volatile("cp.async.wait_group 0;");
        }
        __syncthreads();

        uint32_t sb = sbase + (kt & 1) * GSTG;
#pragma unroll
        for (int s16 = 0; s16 < 2; s16++) {
            const int ko = s16 * 16;
            uint32_t a_hi[2][4], a_lo[2][4], b_hi[4][4], b_lo[4][4];
#pragma unroll
            for (int i = 0; i < 2; i++) {
                uint32_t ar = sb + GA_HI + (wm * 32 + i * 16 + (lane & 15)) * 80
                                 + (ko + (lane >> 4) * 8) * 2;
                ldm_x4(a_hi[i], ar);
                ldm_x4(a_lo[i], ar + (GA_LO - GA_HI));
            }
            const int grp = lane >> 3, rr = lane & 7;
#pragma unroll
            for (int jp = 0; jp < 4; jp++) {
                int row = wn * 64 + jp * 16 + (grp >> 1) * 8 + rr;
                uint32_t br = sb + GB_HI + row * 80 + (ko + (grp & 1) * 8) * 2;
                ldm_x4(b_hi[jp], br);
                ldm_x4(b_lo[jp], br + (GB_LO - GB_HI));
            }
#pragma unroll
            for (int i = 0; i < 2; i++)
#pragma unroll
                for (int j = 0; j < 8; j++) {
                    const int jp = j >> 1, off = (j & 1) * 2;
                    mma16816(c[i][j], a_hi[i], &b_hi[jp][off]);
                    mma16816(c[i][j], a_hi[i], &b_lo[jp][off]);
                    mma16816(c[i][j], a_lo[i], &b_hi[jp][off]);
                }
        }
        __syncthreads();
    }

    const int rowb = bm + wm * 32 + (lane >> 2);
    const int colb = bn + wn * 64 + (lane & 3) * 2;

    if (MODE == 0) {
#pragma unroll
        for (int i = 0; i < 2; i++)
#pragma unroll
            for (int j = 0; j < 8; j++) {
                int row = rowb + i * 16;
                int col = colb + j * 8;
                *(float2*)&C[(size_t)row * N + col]       = make_float2(c[i][j][0], c[i][j][1]);
                *(float2*)&C[(size_t)(row + 8) * N + col] = make_float2(c[i][j][2], c[i][j][3]);
            }
    } else {
#pragma unroll
        for (int i = 0; i < 2; i++)
#pragma unroll
            for (int j = 0; j < 8; j++) {
                int col = colb + j * 8;
#pragma unroll
                for (int rr2 = 0; rr2 < 2; rr2++) {
                    int row = rowb + i * 16 + rr2 * 8;
                    float v0 = c[i][j][rr2 * 2], v1 = c[i][j][rr2 * 2 + 1];
                    if (MODE == 1 || col < 512) {
                        int l = row & (L_ - 1);
                        int p = (col & 63) >> 1;
                        float cc = fc[l * 32 + p], ss = fs[l * 32 + p];
                        float sca = (MODE == 1) ? 0.125f : 1.0f;
                        float o0 = (v0 * cc - v1 * ss) * sca;
                        float o1 = (v0 * ss + v1 * cc) * sca;
                        v0 = o0; v1 = o1;
                    }
                    if (MODE == 1) {
                        split_store(Ohi, Olo, (size_t)row * N + col, v0, v1);
                    } else {
                        if (col < 512) split_store(Ohi,  Olo,  (size_t)row * 512 + col, v0, v1);
                        else           split_store(O2hi, O2lo, (size_t)row * 512 + col - 512, v0, v1);
                    }
                }
            }
    }
}

// ---------------------------------------------------------------------------
// Tensor-core causal GQA flash attention, bf16x3.
// CTA = 64 queries; 4 warps x 16 rows. Q hoisted into REGISTERS (staged once
// through the stage-0 KV buffer), so smem = 2 KV stages = 73.7KB -> 3 CTAs/SM.
// Warp-level compute identical to the proven round-4/8 kernel.
// ---------------------------------------------------------------------------
#define SROW 72
#define AKV_BYTES  9216                       // one KV array: 64*72*2
#define ASTG_BYTES 36864                      // 4 KV arrays
#define ATTN_SMEM  (2 * ASTG_BYTES)           // 73728

__global__ __launch_bounds__(128, 3) void attn_mma(
    const __nv_bfloat16* __restrict__ Qhi, const __nv_bfloat16* __restrict__ Qlo,
    const __nv_bfloat16* __restrict__ Khi, const __nv_bfloat16* __restrict__ Klo,
    const __nv_bfloat16* __restrict__ Vhi, const __nv_bfloat16* __restrict__ Vlo,
    __nv_bfloat16* __restrict__ Ohi, __nv_bfloat16* __restrict__ Olo)
{
    extern __shared__ __align__(16) char smem_raw[];
    const uint32_t sb = (uint32_t)__cvta_generic_to_shared(smem_raw);
    const int qb  = (int)(gridDim.x - 1 - blockIdx.x);   // heavy tiles first
    const int h   = blockIdx.y;
    const int b   = blockIdx.z;
    const int kvh = h >> 2;
    const int tid  = threadIdx.x;
    const int lane = tid & 31;
    const int warp = tid >> 5;

    // ---- stage Q through stage-0 buffer, hoist fragments to registers ----
    uint32_t qh[4][4], ql[4][4];
    {
        const size_t qoff = ((size_t)(b * L_ + qb * 64) * H_ + h) * D_;
        const __nv_bfloat16* qs[2] = { Qhi + qoff, Qlo + qoff };
#pragma unroll
        for (int arr = 0; arr < 2; arr++)
#pragma unroll
            for (int it = 0; it < 4; it++) {
                int idx = tid + it * 128, row = idx >> 3, ch = idx & 7;
                uint32_t dst = sb + arr * AKV_BYTES + (row * SROW + ch * 8) * 2;
                const void* src = qs[arr] + (size_t)row * (H_ * D_) + ch * 8;
                CP_ASYNC16(dst, src);
            }
        asm volatile("cp.async.commit_group;");
        asm volatile("cp.async.wait_group 0;");
        __syncthreads();
#pragma unroll
        for (int ks = 0; ks < 4; ks++) {
            uint32_t qa = sb + ((warp * 16 + (lane & 15)) * SROW
                                + ks * 16 + (lane >> 4) * 8) * 2;
            ldm_x4(qh[ks], qa);
            ldm_x4(ql[ks], qa + AKV_BYTES);
        }
        __syncthreads();   // all warps done reading before KV overwrites
    }

    auto load_kv = [&](int stg, int kb) {
        const size_t koff = ((size_t)(b * L_ + kb * 64) * KVH_ + kvh) * D_;
        const __nv_bfloat16* srcs[4] = { Khi + koff, Klo + koff, Vhi + koff, Vlo + koff };
        uint32_t base = sb + stg * ASTG_BYTES;
#pragma unroll
        for (int arr = 0; arr < 4; arr++)
#pragma unroll
            for (int it = 0; it < 4; it++) {
                int idx = tid + it * 128, row = idx >> 3, ch = idx & 7;
                uint32_t dst = base + arr * AKV_BYTES + (row * SROW + ch * 8) * 2;
                const void* src = srcs[arr] + (size_t)row * (KVH_ * D_) + ch * 8;
                CP_ASYNC16(dst, src);
            }
    };
    load_kv(0, 0);
    asm volatile("cp.async.commit_group;");

    float O[8][4];
#pragma unroll
    for (int nt = 0; nt < 8; nt++)
#pragma unroll
        for (int q = 0; q < 4; q++) O[nt][q] = 0.0f;
    float m0 = -1e30f, m1 = -1e30f, l0 = 0.0f, l1 = 0.0f;

    const int grp = lane >> 3;

    for (int kb = 0; kb <= qb; kb++) {
        if (kb < qb) {
            load_kv((kb + 1) & 1, kb + 1);
            asm volatile("cp.async.commit_group;");
            asm volatile("cp.async.wait_group 1;");
        } else {
            asm volatile("cp.async.wait_group 0;");
        }
        __syncthreads();

        const uint32_t stb = sb + (kb & 1) * ASTG_BYTES;

        // ---- S = Qhi*Khi + Qhi*Klo + Qlo*Khi (Q from registers) ----
        float sc[8][4];
#pragma unroll
        for (int nt = 0; nt < 8; nt++)
#pragma unroll
            for (int q = 0; q < 4; q++) sc[nt][q] = 0.0f;

#pragma unroll
        for (int ks = 0; ks < 4; ks++) {
#pragma unroll
            for (int jn = 0; jn < 4; jn++) {
                uint32_t ka = stb + ((jn * 16 + (grp >> 1) * 8 + (lane & 7)) * SROW
                                     + ks * 16 + (grp & 1) * 8) * 2;
                uint32_t bh[4], bl[4];
                ldm_x4(bh, ka);
                ldm_x4(bl, ka + AKV_BYTES);
                mma16816(sc[2 * jn],     qh[ks], &bh[0]);
                mma16816(sc[2 * jn],     qh[ks], &bl[0]);
                mma16816(sc[2 * jn],     ql[ks], &bh[0]);
                mma16816(sc[2 * jn + 1], qh[ks], &bh[2]);
                mma16816(sc[2 * jn + 1], qh[ks], &bl[2]);
                mma16816(sc[2 * jn + 1], ql[ks], &bh[2]);
            }
        }

        // ---- causal mask on diagonal block ----
        const int r0g = qb * 64 + warp * 16 + (lane >> 2);
        if (kb == qb) {
            const int cb = kb * 64 + (lane & 3) * 2;
#pragma unroll
            for (int nt = 0; nt < 8; nt++) {
                int c = cb + nt * 8;
                if (c     > r0g)     sc[nt][0] = -1e30f;
                if (c + 1 > r0g)     sc[nt][1] = -1e30f;
                if (c     > r0g + 8) sc[nt][2] = -1e30f;
                if (c + 1 > r0g + 8) sc[nt][3] = -1e30f;
            }
        }

        // ---- online softmax (rows live in lane quads) ----
        float mx0 = sc[0][0], mx1 = sc[0][2];
#pragma unroll
        for (int nt = 0; nt < 8; nt++) {
            mx0 = fmaxf(mx0, fmaxf(sc[nt][0], sc[nt][1]));
            mx1 = fmaxf(mx1, fmaxf(sc[nt][2], sc[nt][3]));
        }
        mx0 = fmaxf(mx0, __shfl_xor_sync(0xffffffffu, mx0, 1));
        mx0 = fmaxf(mx0, __shfl_xor_sync(0xffffffffu, mx0, 2));
        mx1 = fmaxf(mx1, __shfl_xor_sync(0xffffffffu, mx1, 1));
        mx1 = fmaxf(mx1, __shfl_xor_sync(0xffffffffu, mx1, 2));
        float mn0 = fmaxf(m0, mx0), mn1 = fmaxf(m1, mx1);
        float a0 = __expf(m0 - mn0), a1 = __expf(m1 - mn1);
        m0 = mn0; m1 = mn1;
        float s0 = 0.0f, s1 = 0.0f;
#pragma unroll
        for (int nt = 0; nt < 8; nt++) {
            sc[nt][0] = __expf(sc[nt][0] - mn0);
            sc[nt][1] = __expf(sc[nt][1] - mn0);
            sc[nt][2] = __expf(sc[nt][2] - mn1);
            sc[nt][3] = __expf(sc[nt][3] - mn1);
            s0 += sc[nt][0] + sc[nt][1];
            s1 += sc[nt][2] + sc[nt][3];
        }
        s0 += __shfl_xor_sync(0xffffffffu, s0, 1);
        s0 += __shfl_xor_sync(0xffffffffu, s0, 2);
        s1 += __shfl_xor_sync(0xffffffffu, s1, 1);
        s1 += __shfl_xor_sync(0xffffffffu, s1, 2);
        l0 = l0 * a0 + s0;
        l1 = l1 * a1 + s1;
#pragma unroll
        for (int nt = 0; nt < 8; nt++) {
            O[nt][0] *= a0; O[nt][1] *= a0;
            O[nt][2] *= a1; O[nt][3] *= a1;
        }

        // ---- O += Phi*Vhi + Phi*Vlo + Plo*Vhi (P packed from registers) ----
#pragma unroll
        for (int ks = 0; ks < 4; ks++) {
            uint32_t ph[4], pl[4];
#pragma unroll
            for (int t = 0; t < 2; t++) {
                int nt = 2 * ks + t;
#pragma unroll
                for (int j = 0; j < 2; j++) {
                    float x0 = sc[nt][2 * j], x1 = sc[nt][2 * j + 1];
                    __nv_bfloat16 h0 = __float2bfloat16(x0);
                    __nv_bfloat16 h1 = __float2bfloat16(x1);
                    __nv_bfloat162 hp = __halves2bfloat162(h0, h1);
                    __nv_bfloat162 lp = __halves2bfloat162(
                        __float2bfloat16(x0 - __bfloat162float(h0)),
                        __float2bfloat16(x1 - __bfloat162float(h1)));
                    ph[t * 2 + j] = *(uint32_t*)&hp;
                    pl[t * 2 + j] = *(uint32_t*)&lp;
                }
            }
#pragma unroll
            for (int dj = 0; dj < 4; dj++) {
                uint32_t va = stb + 2 * AKV_BYTES
                            + ((ks * 16 + (grp & 1) * 8 + (lane & 7)) * SROW
                               + dj * 16 + (grp >> 1) * 8) * 2;
                uint32_t vh[4], vl[4];
                ldm_x4_t(vh, va);
                ldm_x4_t(vl, va + AKV_BYTES);
                mma16816(O[2 * dj],     ph, &vh[0]);
                mma16816(O[2 * dj],     ph, &vl[0]);
                mma16816(O[2 * dj],     pl, &vh[0]);
                mma16816(O[2 * dj + 1], ph, &vh[2]);
                mma16816(O[2 * dj + 1], ph, &vl[2]);
                mma16816(O[2 * dj + 1], pl, &vh[2]);
            }
        }
        __syncthreads();
    }

    // ---- epilogue ----
    float i0 = 1.0f / l0, i1 = 1.0f / l1;
    const size_t ro = ((size_t)(b * L_ + qb * 64 + warp * 16 + (lane >> 2)) * H_ + h) * D_
                      + (lane & 3) * 2;
    const size_t r8 = ro + (size_t)8 * H_ * D_;
#pragma unroll
    for (int nt = 0; nt < 8; nt++) {
        split_store(Ohi, Olo, ro + nt * 8, O[nt][0] * i0, O[nt][1] * i0);
        split_store(Ohi, Olo, r8 + nt * 8, O[nt][2] * i1, O[nt][3] * i1);
    }
}

// ---------------------------------------------------------------------------
// Launch
// ---------------------------------------------------------------------------
static inline void run_split(const float* src, __nv_bfloat16* hi, __nv_bfloat16* lo, size_t n)
{
    int n4 = (int)(n / 4);
    split_kernel<<<(n4 + 255) / 256, 256>>>(src, hi, lo, n4);
}

extern "C" void kernel_launch(void* const* d_in, const int* in_sizes, int n_in,
                              void* d_out, int out_size)
{
    const float* x  = (const float*)d_in[0];
    const float* wq = (const float*)d_in[1];
    const float* wk = (const float*)d_in[2];
    const float* wv = (const float*)d_in[3];
    const float* wo = (const float*)d_in[4];
    const float* fc = (const float*)d_in[5];
    const float* fs = (const float*)d_in[6];
    float* out = (float*)d_out;

    __nv_bfloat16 *xhi, *xlo, *wqhi, *wqlo, *wkvhi, *wkvlo, *wohi, *wolo;
    __nv_bfloat16 *ahi, *alo, *qhi, *qlo, *khi, *klo, *vhi, *vlo;
    cudaGetSymbolAddress((void**)&xhi,   g_xhi);   cudaGetSymbolAddress((void**)&xlo,   g_xlo);
    cudaGetSymbolAddress((void**)&wqhi,  g_wqhi);  cudaGetSymbolAddress((void**)&wqlo,  g_wqlo);
    cudaGetSymbolAddress((void**)&wkvhi, g_wkvhi); cudaGetSymbolAddress((void**)&wkvlo, g_wkvlo);
    cudaGetSymbolAddress((void**)&wohi,  g_wohi);  cudaGetSymbolAddress((void**)&wolo,  g_wolo);
    cudaGetSymbolAddress((void**)&ahi,   g_ahi);   cudaGetSymbolAddress((void**)&alo,   g_alo);
    cudaGetSymbolAddress((void**)&qhi,   g_qhi);   cudaGetSymbolAddress((void**)&qlo,   g_qlo);
    cudaGetSymbolAddress((void**)&khi,   g_khi);   cudaGetSymbolAddress((void**)&klo,   g_klo);
    cudaGetSymbolAddress((void**)&vhi,   g_vhi);   cudaGetSymbolAddress((void**)&vlo,   g_vlo);

    const int M = B_ * L_;                       // 4096

    cudaFuncSetAttribute(gemm_bf16x3<0>, cudaFuncAttributeMaxDynamicSharedMemorySize, GEMM_SMEM);
    cudaFuncSetAttribute(gemm_bf16x3<1>, cudaFuncAttributeMaxDynamicSharedMemorySize, GEMM_SMEM);
    cudaFuncSetAttribute(gemm_bf16x3<2>, cudaFuncAttributeMaxDynamicSharedMemorySize, GEMM_SMEM);
    cudaFuncSetAttribute(attn_mma, cudaFuncAttributeMaxDynamicSharedMemorySize, ATTN_SMEM);

    // Splits: x, wq, wk->wkv[0:512], wv->wkv[512:1024], wo
    run_split(x,  xhi,  xlo,  NX);
    run_split(wq, wqhi, wqlo, NWQ);
    run_split(wk, wkvhi,       wkvlo,       NWK);
    run_split(wv, wkvhi + NWK, wkvlo + NWK, NWK);
    run_split(wo, wohi, wolo, NWO);

    // Q projection, fused rope+scale+split epilogue
    gemm_bf16x3<1><<<dim3((H_ * D_) / 128, M / 64), 128, GEMM_SMEM>>>(
        xhi, xlo, wqhi, wqlo, nullptr, qhi, qlo, nullptr, nullptr, fc, fs,
        M, H_ * D_, HID_);

    // K+V combined projection: rope+split K, split V
    gemm_bf16x3<2><<<dim3(1024 / 128, M / 64), 128, GEMM_SMEM>>>(
        xhi, xlo, wkvhi, wkvlo, nullptr, khi, klo, vhi, vlo, fc, fs,
        M, 1024, HID_);

    // Attention (tensor cores, bf16x3, Q-in-registers, 3 CTAs/SM)
    attn_mma<<<dim3(L_ / 64, H_, B_), 128, ATTN_SMEM>>>(
        qhi, qlo, khi, klo, vhi, vlo, ahi, alo);

    // Output projection -> d_out (fp32)
    gemm_bf16x3<0><<<dim3(HID_ / 128, M / 64), 128, GEMM_SMEM>>>(
        ahi, alo, wohi, wolo, out, nullptr, nullptr, nullptr, nullptr, nullptr, nullptr,
        M, HID_, H_ * D_);
}